// round 14
// baseline (speedup 1.0000x reference)
#include <cuda_runtime.h>
#include <cuda_fp16.h>
#include <cstdint>

// GraphSAGE layer, N=8192, D_IN=D_OUT=512 — int8 tensor-core agg
// (mma.sync.m16n8k32.s8, exact s32 accumulation) + fp16 final GEMM,
// 2-stream fork-join overlap.
// out = relu( x @ (W_self@Wc_top) + agg @ (W_nb@Wc_bot) + c )
// agg = (mask @ x) * invdeg, mask = (adj > 0)  (mask EXACT in s8)
// x quantized s8 at scale 24 (deg~4096 averaging -> out rel err ~2e-4 add'l).

#define NN 8192
#define DD 512
#define XSCALE 24.0f
#define INV_XSCALE (1.0f / 24.0f)

// ------------------------------- device globals (no allocations allowed) ----
__device__ __align__(256) signed char g_mask8[(size_t)NN * NN]; // 64 MB 0/1 s8
__device__ __align__(256) signed char g_xqT[(size_t)DD * NN];   // x^T s8 [f][n]
__device__ __align__(256) __half g_Yh[(size_t)NN * 1024];       // [x|agg] hi
__device__ __align__(256) __half g_Yl[(size_t)NN * 1024];       // [x|agg] lo
__device__ __align__(256) __half g_Wf[(size_t)1024 * DD];       // fused W fp16
__device__ float g_c[DD];
__device__ float g_invdeg[NN];

// ------------------------------------------------------------ PTX helpers ---
__device__ __forceinline__ uint32_t smem_u32(const void* p) {
    uint32_t a;
    asm("{ .reg .u64 t; cvta.to.shared.u64 t, %1; cvt.u32.u64 %0, t; }"
        : "=r"(a) : "l"(p));
    return a;
}
#define CP16(dst, src) \
    asm volatile("cp.async.cg.shared.global [%0], [%1], 16;" \
                 :: "r"(dst), "l"(src) : "memory")
#define CP_COMMIT() asm volatile("cp.async.commit_group;" ::: "memory")
#define CP_WAIT1() asm volatile("cp.async.wait_group 1;" ::: "memory")
#define CP_WAIT0() asm volatile("cp.async.wait_group 0;" ::: "memory")

__device__ __forceinline__ void ldsm4(uint32_t* r, uint32_t addr) {
    asm volatile("ldmatrix.sync.aligned.m8n8.x4.shared.b16 {%0,%1,%2,%3}, [%4];"
                 : "=r"(r[0]), "=r"(r[1]), "=r"(r[2]), "=r"(r[3]) : "r"(addr));
}
__device__ __forceinline__ void ldsm4t(uint32_t* r, uint32_t addr) {
    asm volatile("ldmatrix.sync.aligned.m8n8.x4.trans.shared.b16 {%0,%1,%2,%3}, [%4];"
                 : "=r"(r[0]), "=r"(r[1]), "=r"(r[2]), "=r"(r[3]) : "r"(addr));
}
__device__ __forceinline__ void mma_f16(float* d, const uint32_t* a,
                                        const uint32_t* b) {
    asm volatile(
        "mma.sync.aligned.m16n8k16.row.col.f32.f16.f16.f32 "
        "{%0,%1,%2,%3}, {%4,%5,%6,%7}, {%8,%9}, {%0,%1,%2,%3};"
        : "+f"(d[0]), "+f"(d[1]), "+f"(d[2]), "+f"(d[3])
        : "r"(a[0]), "r"(a[1]), "r"(a[2]), "r"(a[3]), "r"(b[0]), "r"(b[1]));
}
__device__ __forceinline__ void mma_s8(int* d, const uint32_t* a,
                                       const uint32_t* b) {
    asm volatile(
        "mma.sync.aligned.m16n8k32.row.col.s32.s8.s8.s32 "
        "{%0,%1,%2,%3}, {%4,%5,%6,%7}, {%8,%9}, {%0,%1,%2,%3};"
        : "+r"(d[0]), "+r"(d[1]), "+r"(d[2]), "+r"(d[3])
        : "r"(a[0]), "r"(a[1]), "r"(a[2]), "r"(a[3]), "r"(b[0]), "r"(b[1]));
}

// ----------------------------- deg + s8 mask fused (1 adj read, 64MB write) -
__global__ void deg_mask_kernel(const int* __restrict__ adj) {
    const int row = blockIdx.x;
    const int4* p = (const int4*)(adj + (size_t)row * NN);
    unsigned* mout = (unsigned*)(g_mask8 + (size_t)row * NN);
    int s = 0;
    for (int i = threadIdx.x; i < NN / 4; i += 256) {
        int4 v = p[i];
        unsigned u = (v.x > 0 ? 1u : 0u) | (v.y > 0 ? 0x100u : 0u) |
                     (v.z > 0 ? 0x10000u : 0u) | (v.w > 0 ? 0x1000000u : 0u);
        s += (v.x > 0) + (v.y > 0) + (v.z > 0) + (v.w > 0);
        mout[i] = u;
    }
    __shared__ int red[256];
    red[threadIdx.x] = s;
    __syncthreads();
    for (int o = 128; o > 0; o >>= 1) {
        if (threadIdx.x < o) red[threadIdx.x] += red[threadIdx.x + o];
        __syncthreads();
    }
    if (threadIdx.x == 0)
        g_invdeg[row] = 1.0f / fmaxf((float)red[0], 1.0f);
}

// -------- x -> Yh/Yl cols 0..511 (node-major) + xqT s8 (feature-major) ------
__global__ void conv_x_kernel(const float* __restrict__ x) {
    __shared__ signed char sq[32][33];
    const int tx = threadIdx.x, ty = threadIdx.y;   // (32, 8)
    const int c0 = blockIdx.x * 32, r0 = blockIdx.y * 32;
#pragma unroll
    for (int i = 0; i < 4; i++) {
        int rl = ty + i * 8;
        int r = r0 + rl, c = c0 + tx;
        float v = x[(size_t)r * DD + c];
        __half h = __float2half(v);
        __half l = __float2half(v - __half2float(h));
        g_Yh[(size_t)r * 1024 + c] = h;
        g_Yl[(size_t)r * 1024 + c] = l;
        float q = fminf(fmaxf(v * XSCALE, -127.0f), 127.0f);
        sq[rl][tx] = (signed char)__float2int_rn(q);
    }
    __syncthreads();
#pragma unroll
    for (int i = 0; i < 4; i++) {
        int rl = ty + i * 8;
        g_xqT[(size_t)(c0 + rl) * NN + r0 + tx] = sq[tx][rl];
    }
}

// ---------- small 512^3 GEMMs (both halves, grid.z) -> Wf fp16 --------------
__global__ void small_gemm512(const float* __restrict__ W_self,
                              const float* __restrict__ W_nb,
                              const float* __restrict__ W_comb) {
    const int half = blockIdx.z;
    const float* A = half ? W_nb : W_self;
    const float* B = W_comb + (size_t)half * 512 * 512;
    __shared__ float As[16][68];
    __shared__ float Bs[16][64];
    const int t = threadIdx.x;
    const int bm = blockIdx.y * 64, bn = blockIdx.x * 64;
    const int ty = t >> 4, tx = t & 15;
    float acc[4][4] = {};
    for (int k0 = 0; k0 < 512; k0 += 16) {
        {
            int row = t >> 2, c4 = t & 3;
            float4 v = *(const float4*)(A + (size_t)(bm + row) * 512 + k0 + c4 * 4);
            As[c4 * 4 + 0][row] = v.x;
            As[c4 * 4 + 1][row] = v.y;
            As[c4 * 4 + 2][row] = v.z;
            As[c4 * 4 + 3][row] = v.w;
        }
        {
            int kr = t >> 4, c4 = t & 15;
            *(float4*)&Bs[kr][c4 * 4] =
                *(const float4*)(B + (size_t)(k0 + kr) * 512 + bn + c4 * 4);
        }
        __syncthreads();
#pragma unroll
        for (int k = 0; k < 16; k++) {
            float4 av = *(const float4*)&As[k][ty * 4];
            float4 bv = *(const float4*)&Bs[k][tx * 4];
            float a[4] = {av.x, av.y, av.z, av.w};
            float b[4] = {bv.x, bv.y, bv.z, bv.w};
#pragma unroll
            for (int i = 0; i < 4; i++)
#pragma unroll
                for (int j = 0; j < 4; j++) acc[i][j] += a[i] * b[j];
        }
        __syncthreads();
    }
#pragma unroll
    for (int i = 0; i < 4; i++)
#pragma unroll
        for (int j = 0; j < 4; j++) {
            int kk = half * 512 + bm + ty * 4 + i;   // K index of final GEMM
            int n = bn + tx * 4 + j;
            g_Wf[(size_t)kk * 512 + n] = __float2half(acc[i][j]);
        }
}

// ----------------------------------------------------------- fused bias -----
__global__ void bias_kernel(const float* __restrict__ b_self,
                            const float* __restrict__ b_nb,
                            const float* __restrict__ b_comb,
                            const float* __restrict__ Wc) {
    const int n = blockIdx.x;
    float s = 0.0f;
    for (int o = threadIdx.x; o < 1024; o += 256) {
        float b = (o < 512) ? b_self[o] : b_nb[o - 512];
        s += b * Wc[(size_t)o * 512 + n];
    }
    __shared__ float red[256];
    red[threadIdx.x] = s;
    __syncthreads();
    for (int o = 128; o > 0; o >>= 1) {
        if (threadIdx.x < o) red[threadIdx.x] += red[threadIdx.x + o];
        __syncthreads();
    }
    if (threadIdx.x == 0) g_c[n] = red[0] + b_comb[n];
}

// --------------------- agg GEMM: s8 mma.sync m16n8k32, exact s32 accum ------
// BM=128, BN=128, BK=64 (2 k32-steps); 8 warps (2m x 4n), warp tile 64x32.
// A = mask s8 row-major tile; B = xqT s8 [feature][node] row-major tile
// (= col-major B operand). s8 k32 fragments are b16 k16 fragments
// byte-reinterpreted -> plain ldsm4 (non-trans) loads both operands.
// Epilogue: * invdeg/XSCALE -> Yh/Yl cols 512..1023 (fp16 hi/lo split).
#define A8_T (128 * 80)   // bytes per A tile (64 data + 16 pad per row)
#define B8_T (128 * 80)   // bytes per B tile
#define AGG_SMEM (2 * (A8_T + B8_T))                 // 40,960 B

__global__ void __launch_bounds__(256, 2) agg_gemm() {
    constexpr int NCH = 128;                          // K = 8192 / 64
    extern __shared__ char sm8[];
    const uint32_t sb = smem_u32(sm8);
    const int tid = threadIdx.x, lane = tid & 31, wid = tid >> 5;
    const int wm = wid & 1, wn = wid >> 1;
    const int bm = blockIdx.y * 128, bn = blockIdx.x * 128;

    int acc[4][4][4] = {};

    auto fill = [&](int k0, int buf) {
        const uint32_t base = sb + buf * (A8_T + B8_T);
#pragma unroll
        for (int j = 0; j < 2; j++) {                 // A: 128 rows x 64 B
            int idx = tid + j * 256;
            int row = idx >> 2, q = idx & 3;
            CP16(base + row * 80 + q * 16,
                 g_mask8 + (size_t)(bm + row) * NN + k0 + q * 16);
        }
#pragma unroll
        for (int j = 0; j < 2; j++) {                 // B: 128 n-rows x 64 B
            int idx = tid + j * 256;
            int row = idx >> 2, q = idx & 3;
            CP16(base + A8_T + row * 80 + q * 16,
                 g_xqT + (size_t)(bn + row) * NN + k0 + q * 16);
        }
    };

    fill(0, 0);
    CP_COMMIT();

    for (int c = 0; c < NCH; ++c) {
        const int buf = c & 1;
        if (c + 1 < NCH) {
            fill((c + 1) * 64, buf ^ 1);
            CP_COMMIT();
            CP_WAIT1();
        } else {
            CP_WAIT0();
        }
        __syncthreads();

        const uint32_t ab = sb + buf * (A8_T + B8_T);
        const uint32_t bb = ab + A8_T;
#pragma unroll
        for (int ks = 0; ks < 2; ks++) {
            uint32_t Af[4][4];
            uint32_t Bf[4][2];
            const uint32_t seg = ks * 32 + ((lane >> 4) << 4);
#pragma unroll
            for (int i = 0; i < 4; i++) {
                int row = wm * 64 + i * 16 + (lane & 15);
                ldsm4(Af[i], ab + row * 80 + seg);
            }
#pragma unroll
            for (int jp = 0; jp < 2; jp++) {
                int nrow = wn * 32 + jp * 16 + (lane & 15);
                uint32_t r[4];
                ldsm4(r, bb + nrow * 80 + seg);
                Bf[jp * 2][0] = r[0];     Bf[jp * 2][1] = r[2];
                Bf[jp * 2 + 1][0] = r[1]; Bf[jp * 2 + 1][1] = r[3];
            }
#pragma unroll
            for (int i = 0; i < 4; i++)
#pragma unroll
                for (int jn = 0; jn < 4; jn++)
                    mma_s8(acc[i][jn], Af[i], Bf[jn]);
        }
        __syncthreads();
    }

    // --------------------------------------------------------- epilogue ----
    const int gid = lane >> 2, tig = lane & 3;
#pragma unroll
    for (int i = 0; i < 4; i++)
#pragma unroll
        for (int h = 0; h < 2; h++) {
            const int gr = bm + wm * 64 + i * 16 + gid + h * 8;
            const float s = g_invdeg[gr] * INV_XSCALE;
#pragma unroll
            for (int jn = 0; jn < 4; jn++) {
                int col = bn + wn * 32 + jn * 8 + tig * 2;
                float v0 = (float)acc[i][jn][h * 2 + 0] * s;
                float v1 = (float)acc[i][jn][h * 2 + 1] * s;
                __half h0 = __float2half(v0);
                __half h1 = __float2half(v1);
                __half2 hp, lp;
                hp.x = h0; hp.y = h1;
                lp.x = __float2half(v0 - __half2float(h0));
                lp.y = __float2half(v1 - __half2float(h1));
                *(__half2*)&g_Yh[(size_t)gr * 1024 + 512 + col] = hp;
                *(__half2*)&g_Yl[(size_t)gr * 1024 + 512 + col] = lp;
            }
        }
}

// ------------------- final GEMM: (Yh+Yl) @ Wf, +bias, relu (fp16, BK=64) ----
#define SA_T (128 * 72)   // halfs per A tile
#define SB_T (64 * 136)   // halfs per B tile
#define FIN_SMEM ((2 * 2 * SA_T + 2 * SB_T) * 2)     // 108,544 B

__global__ void __launch_bounds__(256, 2) fin_gemm(float* __restrict__ outp) {
    constexpr int NCH = 16;                           // K = 1024 / 64
    constexpr int BOFF = 4 * SA_T;
    extern __shared__ __half smf[];
    const uint32_t sb = smem_u32(smf);
    const int tid = threadIdx.x, lane = tid & 31, wid = tid >> 5;
    const int wm = wid & 1, wn = wid >> 1;
    const int bm = blockIdx.y * 128, bn = blockIdx.x * 128;
    const __half* Ap[2] = {g_Yh, g_Yl};

    float acc[4][4][4] = {};

    auto fill = [&](int k0, int buf) {
#pragma unroll
        for (int a = 0; a < 2; a++)
#pragma unroll
            for (int j = 0; j < 4; j++) {
                int idx = tid + j * 256;
                int row = idx >> 3, q = idx & 7;
                CP16(sb + ((buf * 2 + a) * SA_T + row * 72 + q * 8) * 2,
                     Ap[a] + (size_t)(bm + row) * 1024 + k0 + q * 8);
            }
#pragma unroll
        for (int j = 0; j < 4; j++) {
            int idx = tid + j * 256;
            int row = idx >> 4, q = idx & 15;
            CP16(sb + (BOFF + buf * SB_T + row * 136 + q * 8) * 2,
                 g_Wf + (size_t)(k0 + row) * DD + bn + q * 8);
        }
    };

    fill(0, 0);
    CP_COMMIT();
    for (int c = 0; c < NCH; ++c) {
        const int buf = c & 1;
        if (c + 1 < NCH) { fill((c + 1) * 64, buf ^ 1); CP_COMMIT(); CP_WAIT1(); }
        else CP_WAIT0();
        __syncthreads();
#pragma unroll
        for (int ks = 0; ks < 4; ks++) {
            uint32_t Af[2][4][4];
            uint32_t Bf[4][2];
#pragma unroll
            for (int a = 0; a < 2; a++)
#pragma unroll
                for (int i = 0; i < 4; i++) {
                    int row = wm * 64 + i * 16 + (lane & 15);
                    int col = ks * 16 + ((lane >> 4) << 3);
                    ldsm4(Af[a][i],
                          sb + ((buf * 2 + a) * SA_T + row * 72 + col) * 2);
                }
#pragma unroll
            for (int jp = 0; jp < 2; jp++) {
                int row = ks * 16 + (lane & 15);
                int col = wn * 32 + jp * 16 + ((lane >> 4) << 3);
                uint32_t r[4];
                ldsm4t(r, sb + (BOFF + buf * SB_T + row * 136 + col) * 2);
                Bf[jp * 2][0] = r[0];     Bf[jp * 2][1] = r[1];
                Bf[jp * 2 + 1][0] = r[2]; Bf[jp * 2 + 1][1] = r[3];
            }
#pragma unroll
            for (int a = 0; a < 2; a++)
#pragma unroll
                for (int i = 0; i < 4; i++)
#pragma unroll
                    for (int jn = 0; jn < 4; jn++)
                        mma_f16(acc[i][jn], Af[a][i], Bf[jn]);
        }
        __syncthreads();
    }

    const int gid = lane >> 2, tig = lane & 3;
#pragma unroll
    for (int i = 0; i < 4; i++)
#pragma unroll
        for (int h = 0; h < 2; h++) {
            const int gr = bm + wm * 64 + i * 16 + gid + h * 8;
#pragma unroll
            for (int jn = 0; jn < 4; jn++) {
                int col = bn + wn * 32 + jn * 8 + tig * 2;
                float2 o;
                o.x = fmaxf(acc[i][jn][h * 2 + 0] + g_c[col], 0.0f);
                o.y = fmaxf(acc[i][jn][h * 2 + 1] + g_c[col + 1], 0.0f);
                *(float2*)&outp[(size_t)gr * 512 + col] = o;
            }
        }
}

// ---------------------------------------------------------------- launch ----
extern "C" void kernel_launch(void* const* d_in, const int* in_sizes, int n_in,
                              void* d_out, int out_size) {
    const float* x      = (const float*)d_in[0];
    const int*   adj    = (const int*)d_in[1];
    const float* W_self = (const float*)d_in[2];
    const float* b_self = (const float*)d_in[3];
    const float* W_nb   = (const float*)d_in[4];
    const float* b_nb   = (const float*)d_in[5];
    const float* W_comb = (const float*)d_in[6];
    const float* b_comb = (const float*)d_in[7];
    float* out = (float*)d_out;

    static cudaStream_t sW = 0, sX = 0;
    static cudaEvent_t evR = 0, evW = 0, evX = 0;
    static int inited = 0;
    if (!inited) {
        inited = 1;
        cudaFuncSetAttribute(agg_gemm,
                             cudaFuncAttributeMaxDynamicSharedMemorySize, AGG_SMEM);
        cudaFuncSetAttribute(fin_gemm,
                             cudaFuncAttributeMaxDynamicSharedMemorySize, FIN_SMEM);
        bool ok =
            cudaStreamCreateWithFlags(&sW, cudaStreamNonBlocking) == cudaSuccess &&
            cudaStreamCreateWithFlags(&sX, cudaStreamNonBlocking) == cudaSuccess &&
            cudaEventCreateWithFlags(&evR, cudaEventDisableTiming) == cudaSuccess &&
            cudaEventCreateWithFlags(&evW, cudaEventDisableTiming) == cudaSuccess &&
            cudaEventCreateWithFlags(&evX, cudaEventDisableTiming) == cudaSuccess;
        if (!ok) { sW = 0; sX = 0; }
    }

    if (sW) {
        // fork
        cudaEventRecord(evR, 0);
        cudaStreamWaitEvent(sW, evR, 0);
        cudaStreamWaitEvent(sX, evR, 0);
        // side stream W: weight fusion chain (joins before final GEMM)
        small_gemm512<<<dim3(8, 8, 2), 256, 0, sW>>>(W_self, W_nb, W_comb);
        bias_kernel<<<512, 256, 0, sW>>>(b_self, b_nb, b_comb, W_comb);
        cudaEventRecord(evW, sW);
        // side stream X: x conversion (joins before agg GEMM)
        conv_x_kernel<<<dim3(16, 256), dim3(32, 8), 0, sX>>>(x);
        cudaEventRecord(evX, sX);
        // main stream
        deg_mask_kernel<<<NN, 256>>>(adj);
        cudaStreamWaitEvent(0, evX, 0);
        agg_gemm<<<dim3(4, 64), 256, AGG_SMEM>>>();
        cudaStreamWaitEvent(0, evW, 0);
        fin_gemm<<<dim3(4, 64), 256, FIN_SMEM>>>(out);
    } else {
        deg_mask_kernel<<<NN, 256>>>(adj);
        conv_x_kernel<<<dim3(16, 256), dim3(32, 8)>>>(x);
        small_gemm512<<<dim3(8, 8, 2), 256>>>(W_self, W_nb, W_comb);
        bias_kernel<<<512, 256>>>(b_self, b_nb, b_comb, W_comb);
        agg_gemm<<<dim3(4, 64), 256, AGG_SMEM>>>();
        fin_gemm<<<dim3(4, 64), 256, FIN_SMEM>>>(out);
    }
}